// round 13
// baseline (speedup 1.0000x reference)
#include <cuda_runtime.h>
#include <cuda_bf16.h>
#include <math.h>

#define H 128
#define MAXN 100000
#define BN_EPS 1e-5f

// ---------------- scratch (device globals: no allocation allowed) -------------
__device__ __align__(16) float g_hu[(size_t)MAXN * H];
__device__ __align__(16) float g_hr[(size_t)MAXN * H];
__device__ __align__(16) float g_aggR[(size_t)MAXN * H];
__device__ __align__(16) float g_aggU[(size_t)MAXN * H];
__device__ __align__(16) __nv_bfloat16 g_Pub[(size_t)MAXN * H];  // Pu = hu @ epW1[0:128]
__device__ __align__(16) __nv_bfloat16 g_Prb[(size_t)MAXN * H];  // Pr = hr @ epW1[128:256]
__device__ __align__(16) float g_cu[MAXN];   // float in-degree counts (user dst)
__device__ __align__(16) float g_cr[MAXN];   // float in-degree counts (recipient dst)

// ---------------- small utility kernels --------------------------------------
// zero aggR, aggU, cr, cu in one launch (float4 units)
__global__ void zero_all_kernel(float4* __restrict__ p1, int n1, float4* __restrict__ p2, int n2,
                                float4* __restrict__ p3, int n3, float4* __restrict__ p4, int n4) {
    int i = blockIdx.x * blockDim.x + threadIdx.x;
    float4 z = make_float4(0.f, 0.f, 0.f, 0.f);
    if (i < n1) p1[i] = z;
    else if ((i -= n1) < n2) p2[i] = z;
    else if ((i -= n2) < n3) p3[i] = z;
    else if ((i -= n3) < n4) p4[i] = z;
}

// y[n,H] = x[n,32] @ W[32,H] + b ; both node types in one launch
__global__ void proj2_kernel(const float* __restrict__ xu, const float* __restrict__ Wu,
                             const float* __restrict__ bu, float* __restrict__ yu, int nu,
                             const float* __restrict__ xr, const float* __restrict__ Wr,
                             const float* __restrict__ br, float* __restrict__ yr, int nr) {
    int i = blockIdx.x * blockDim.x + threadIdx.x;
    const float* x; const float* W; const float* b; float* y;
    if (i < nu * H) { x = xu; W = Wu; b = bu; y = yu; }
    else if (i < (nu + nr) * H) { i -= nu * H; x = xr; W = Wr; b = br; y = yr; }
    else return;
    int row = i >> 7;
    int c = i & (H - 1);
    const float* xr_ = x + (size_t)row * 32;
    float acc = b[c];
#pragma unroll
    for (int k = 0; k < 32; k++) acc = fmaf(xr_[k], W[k * H + c], acc);
    y[i] = acc;
}

// Both scatters in one launch; fp32 v4 reductions; 4 edges/warp (MLP=4).
// doCount: lane 0 also accumulates float in-degree counts.
__global__ void scatter2_kernel(const float* __restrict__ hu, const float* __restrict__ hr,
                                const int* __restrict__ utSrc, const int* __restrict__ utDst,
                                const int* __restrict__ ruSrc, const int* __restrict__ ruDst,
                                float* __restrict__ aggR, float* __restrict__ aggU,
                                float* __restrict__ cr, float* __restrict__ cu,
                                int doCount, int E) {
    int t = blockIdx.x * blockDim.x + threadIdx.x;
    int warp = t >> 5;
    int j = t & 31;
    int e0 = warp * 4;
    if (e0 >= 2 * E) return;

    const float* hp[4];
    float* ap[4];
    bool ok[4];
#pragma unroll
    for (int k = 0; k < 4; k++) {
        int e = e0 + k;
        ok[k] = e < 2 * E;
        if (ok[k]) {
            int s, d;
            if (e < E) {
                s = utSrc[e]; d = utDst[e];
                hp[k] = hu + (size_t)s * H;
                ap[k] = aggR + (size_t)d * H;
                if (doCount && j == 0) atomicAdd(&cr[d], 1.0f);
            } else {
                s = ruSrc[e - E]; d = ruDst[e - E];
                hp[k] = hr + (size_t)s * H;
                ap[k] = aggU + (size_t)d * H;
                if (doCount && j == 0) atomicAdd(&cu[d], 1.0f);
            }
        }
    }
    float4 v[4];
#pragma unroll
    for (int k = 0; k < 4; k++)
        if (ok[k]) v[k] = ((const float4*)hp[k])[j];
#pragma unroll
    for (int k = 0; k < 4; k++)
        if (ok[k]) {
            float* p = ap[k] + j * 4;
            asm volatile("red.global.add.v4.f32 [%0], {%1, %2, %3, %4};"
                         :: "l"(p), "f"(v[k].x), "f"(v[k].y), "f"(v[k].z), "f"(v[k].w) : "memory");
        }
}

// ------------------------ bf16 tensor-core GEMM -------------------------------
__device__ __forceinline__ void mma16816(float* d, const unsigned* a, unsigned b0, unsigned b1) {
    asm volatile("mma.sync.aligned.m16n8k16.row.col.f32.bf16.bf16.f32 "
                 "{%0,%1,%2,%3}, {%4,%5,%6,%7}, {%8,%9}, {%0,%1,%2,%3};"
                 : "+f"(d[0]), "+f"(d[1]), "+f"(d[2]), "+f"(d[3])
                 : "r"(a[0]), "r"(a[1]), "r"(a[2]), "r"(a[3]), "r"(b0), "r"(b1));
}

// Two independent SAGE-layer problems fused in one launch, split by block range.
struct GemmPair {
    const float* A[2];        // fp32 agg
    const float* cnt[2];      // float in-degree counts (inverse folded here)
    float* Bh[2];             // fp32 h (residual, in-place)
    const float* W1[2];
    const float* W2[2];
    const float* bias[2];
    const float* bg[2];
    const float* bb[2];
    const float* bm[2];
    const float* bv[2];
    const float* Wep[2];      // MODE2: edge-predictor W1 half
    __nv_bfloat16* Outb[2];   // MODE2: bf16 P output
    int M[2];
    int split;
    int zeroA;                // zero agg rows after staging (prepare next layer)
};

// MODE 1: Bh = relu(bn( [A/max(cnt,1) | Bh] @ [W1;W2] + bias )) + Bh   (K=256)
// MODE 2: same, PLUS fused P = bf16(new_h) @ Wep written to Outb (bf16)
template <int MODE>
__global__ void __launch_bounds__(256)
mma_pair_kernel(GemmPair p) {
    constexpr int K = 256;
    constexpr int KPAD = K + 8;
    extern __shared__ __align__(16) unsigned char smraw[];
    __nv_bfloat16* sWt = (__nv_bfloat16*)smraw;                 // [128][KPAD] (n-major)
    __nv_bfloat16* sA = sWt + 128 * KPAD;                       // [128][KPAD] (row-major)
    float* sS = (float*)(sA + 128 * KPAD);                      // 128
    float* sT = sS + 128;                                       // 128
    __nv_bfloat16* sWep = (__nv_bfloat16*)(sT + 128);           // MODE2: [128][136] (n-major)

    int hsel = blockIdx.x >= p.split ? 1 : 0;
    int b0 = hsel ? blockIdx.x - p.split : blockIdx.x;
    int nb = hsel ? gridDim.x - p.split : p.split;
    const float* A = p.A[hsel];
    const float* cnt = p.cnt[hsel];
    float* Bh = p.Bh[hsel];
    const float* W1 = p.W1[hsel];
    const float* W2 = p.W2[hsel];
    int M = p.M[hsel];

    int tid = threadIdx.x;
    int lane = tid & 31;
    int wid = tid >> 5;
    int warp_m = wid >> 1;
    int warp_n = wid & 1;

    for (int i = tid; i < K * 128; i += 256) {
        int k = i >> 7;
        int n = i & 127;
        float w = (k >= 128) ? W2[(k - 128) * 128 + n] : W1[k * 128 + n];
        sWt[n * KPAD + k] = __float2bfloat16(w);
    }
    if (MODE == 2) {
        const float* Wep = p.Wep[hsel];
        for (int i = tid; i < 128 * 128; i += 256) {
            int k = i >> 7;
            int n = i & 127;
            sWep[n * 136 + k] = __float2bfloat16(Wep[k * 128 + n]);
        }
    }
    if (tid < 128) {
        float s = p.bg[hsel][tid] * rsqrtf(p.bv[hsel][tid] + BN_EPS);
        sS[tid] = s;
        sT[tid] = (p.bias[hsel][tid] - p.bm[hsel][tid]) * s + p.bb[hsel][tid];
    }
    __syncthreads();

    int numTiles = (M + 127) >> 7;
    for (int tile = b0; tile < numTiles; tile += nb) {
        int row0 = tile * 128;
        for (int i = tid; i < 128 * 32; i += 256) {
            int r = i >> 5;
            int q = i & 31;
            int row = row0 + r;
            float4 a = make_float4(0.f, 0.f, 0.f, 0.f);
            if (row < M) {
                a = ((const float4*)(A + (size_t)row * H))[q];
                float sc = 1.0f / fmaxf(cnt[row], 1.0f);
                a.x *= sc; a.y *= sc; a.z *= sc; a.w *= sc;
                if (p.zeroA)
                    ((float4*)A)[(size_t)row * 32 + q] = make_float4(0.f, 0.f, 0.f, 0.f);
            }
            __nv_bfloat162 p0 = __floats2bfloat162_rn(a.x, a.y);
            __nv_bfloat162 p1 = __floats2bfloat162_rn(a.z, a.w);
            *(uint2*)(sA + r * KPAD + q * 4) = make_uint2(*(unsigned*)&p0, *(unsigned*)&p1);
            float4 hv = make_float4(0.f, 0.f, 0.f, 0.f);
            if (row < M) hv = ((const float4*)(Bh + (size_t)row * H))[q];
            __nv_bfloat162 q0 = __floats2bfloat162_rn(hv.x, hv.y);
            __nv_bfloat162 q1 = __floats2bfloat162_rn(hv.z, hv.w);
            *(uint2*)(sA + r * KPAD + 128 + q * 4) = make_uint2(*(unsigned*)&q0, *(unsigned*)&q1);
        }
        __syncthreads();

        float acc[2][8][4];
#pragma unroll
        for (int mt = 0; mt < 2; mt++)
#pragma unroll
            for (int nt = 0; nt < 8; nt++)
#pragma unroll
                for (int j = 0; j < 4; j++) acc[mt][nt][j] = 0.f;

        int ar = warp_m * 32 + (lane >> 2);
        int ac = (lane & 3) * 2;
#pragma unroll
        for (int ks = 0; ks < 16; ks++) {
            int kb = ks * 16;
            unsigned a[2][4];
#pragma unroll
            for (int mt = 0; mt < 2; mt++) {
                const __nv_bfloat16* base = sA + (ar + mt * 16) * KPAD + kb + ac;
                a[mt][0] = *(const unsigned*)(base);
                a[mt][1] = *(const unsigned*)(base + 8 * KPAD);
                a[mt][2] = *(const unsigned*)(base + 8);
                a[mt][3] = *(const unsigned*)(base + 8 * KPAD + 8);
            }
#pragma unroll
            for (int nt = 0; nt < 8; nt++) {
                const __nv_bfloat16* bbase = sWt + (warp_n * 64 + nt * 8 + (lane >> 2)) * KPAD + kb + ac;
                unsigned b0 = *(const unsigned*)(bbase);
                unsigned b1 = *(const unsigned*)(bbase + 8);
                mma16816(acc[0][nt], a[0], b0, b1);
                mma16816(acc[1][nt], a[1], b0, b1);
            }
        }

        if (MODE == 2) __syncthreads();   // all sA reads done before epilogue overwrites it

        int rbase = row0 + warp_m * 32 + (lane >> 2);
        int cbase = warp_n * 64 + (lane & 3) * 2;
#pragma unroll
        for (int mt = 0; mt < 2; mt++) {
#pragma unroll
            for (int half = 0; half < 2; half++) {
                int row = rbase + mt * 16 + half * 8;
                if (row < M) {
#pragma unroll
                    for (int nt = 0; nt < 8; nt++) {
                        int c = cbase + nt * 8;
                        float v0 = acc[mt][nt][half * 2 + 0];
                        float v1 = acc[mt][nt][half * 2 + 1];
                        v0 = v0 * sS[c] + sT[c];
                        v1 = v1 * sS[c + 1] + sT[c + 1];
                        float2 hres = *(const float2*)(Bh + (size_t)row * H + c);
                        float2 o = make_float2(fmaxf(v0, 0.f) + hres.x, fmaxf(v1, 0.f) + hres.y);
                        *(float2*)(Bh + (size_t)row * H + c) = o;
                        if (MODE == 2) {
                            int lr = row - row0;
                            __nv_bfloat162 ob = __floats2bfloat162_rn(o.x, o.y);
                            *(unsigned*)(sA + lr * KPAD + c) = *(unsigned*)&ob;
                        }
                    }
                }
            }
        }

        if (MODE == 2) {
            __syncthreads();   // new-h tile fully in sA cols [0,128)
            __nv_bfloat16* Outb = p.Outb[hsel];
            float acc2[2][8][4];
#pragma unroll
            for (int mt = 0; mt < 2; mt++)
#pragma unroll
                for (int nt = 0; nt < 8; nt++)
#pragma unroll
                    for (int j = 0; j < 4; j++) acc2[mt][nt][j] = 0.f;
#pragma unroll
            for (int ks = 0; ks < 8; ks++) {
                int kb = ks * 16;
                unsigned a[2][4];
#pragma unroll
                for (int mt = 0; mt < 2; mt++) {
                    const __nv_bfloat16* base = sA + (ar + mt * 16) * KPAD + kb + ac;
                    a[mt][0] = *(const unsigned*)(base);
                    a[mt][1] = *(const unsigned*)(base + 8 * KPAD);
                    a[mt][2] = *(const unsigned*)(base + 8);
                    a[mt][3] = *(const unsigned*)(base + 8 * KPAD + 8);
                }
#pragma unroll
                for (int nt = 0; nt < 8; nt++) {
                    const __nv_bfloat16* bbase = sWep + (warp_n * 64 + nt * 8 + (lane >> 2)) * 136 + kb + ac;
                    unsigned b0 = *(const unsigned*)(bbase);
                    unsigned b1 = *(const unsigned*)(bbase + 8);
                    mma16816(acc2[0][nt], a[0], b0, b1);
                    mma16816(acc2[1][nt], a[1], b0, b1);
                }
            }
#pragma unroll
            for (int mt = 0; mt < 2; mt++) {
#pragma unroll
                for (int half = 0; half < 2; half++) {
                    int row = rbase + mt * 16 + half * 8;
                    if (row < M) {
#pragma unroll
                        for (int nt = 0; nt < 8; nt++) {
                            int c = cbase + nt * 8;
                            __nv_bfloat162 ob = __floats2bfloat162_rn(acc2[mt][nt][half * 2 + 0],
                                                                      acc2[mt][nt][half * 2 + 1]);
                            *(unsigned*)(Outb + (size_t)row * H + c) = *(unsigned*)&ob;
                        }
                    }
                }
            }
        }
        __syncthreads();
    }
}

// Fused edge predictor; Pu/Pr gathered as bf16; layer 2 on bf16 mma; layer 3 warp-parallel.
__global__ void __launch_bounds__(256, 2)
edgepred_kernel(const int* __restrict__ utSrc, const int* __restrict__ utDst,
                const float* __restrict__ ea,
                const __nv_bfloat16* __restrict__ Pub, const __nv_bfloat16* __restrict__ Prb,
                const float* __restrict__ W1c, const float* __restrict__ b1,
                const float* __restrict__ bng, const float* __restrict__ bnb,
                const float* __restrict__ bnm, const float* __restrict__ bnv,
                const float* __restrict__ W2, const float* __restrict__ b2,
                const float* __restrict__ W3, const float* __restrict__ b3,
                float* __restrict__ outp, int E) {
    extern __shared__ __align__(16) unsigned char smroot[];
    float* sW1c = (float*)smroot;                 // 2048 f32
    float* xs = sW1c + 2048;                      // 32*128 f32 (reused as h2 [32][65])
    float* sea = xs + 4096;                       // 32*16 f32
    float* pb1 = sea + 512;                       // 128
    float* ps1 = pb1 + 128;                       // 128
    float* pt1 = ps1 + 128;                       // 128
    float* pb2 = pt1 + 128;                       // 64
    float* pW3 = pb2 + 64;                        // 64
    float* pb3 = pW3 + 64;                        // 4 (padded)
    __nv_bfloat16* sW2b = (__nv_bfloat16*)(pb3 + 4);   // [64][136] bf16, n-major
    __nv_bfloat16* h1b = sW2b + 64 * 136;              // [32][136] bf16

    int tid = threadIdx.x;
    int lane = tid & 31;
    int w = tid >> 5;

    for (int i = tid; i < 2048 / 4; i += 256)
        ((float4*)sW1c)[i] = ((const float4*)W1c)[i];
    for (int i = tid; i < 128 * 64; i += 256) {
        int k = i >> 6;
        int n = i & 63;
        sW2b[n * 136 + k] = __float2bfloat16(W2[k * 64 + n]);
    }
    if (tid < 128) {
        pb1[tid] = b1[tid];
        float s = bng[tid] * rsqrtf(bnv[tid] + BN_EPS);
        ps1[tid] = s;
        pt1[tid] = bnb[tid] - bnm[tid] * s;
    } else if (tid < 192) {
        pb2[tid - 128] = b2[tid - 128];
    } else {
        pW3[tid - 192] = W3[tid - 192];
    }
    if (tid == 0) pb3[0] = b3[0];
    __syncthreads();

    int tc = tid & 31;
    int te = tid >> 5;
    int c0 = tc * 4;
    int e0 = te * 4;
    int mt2 = w >> 2;
    int nq2 = w & 3;

    int numTiles = E / 32;
    for (int tile = blockIdx.x; tile < numTiles; tile += gridDim.x) {
        int base = tile * 32;
#pragma unroll
        for (int i = 0; i < 4; i++) {
            int e = w * 4 + i;
            int eg = base + e;
            int s = utSrc[eg];
            int d = utDst[eg];
            uint2 pa = ((const uint2*)(Pub + (size_t)s * H))[lane];
            uint2 pbv = ((const uint2*)(Prb + (size_t)d * H))[lane];
            float2 alo = __bfloat1622float2(*reinterpret_cast<__nv_bfloat162*>(&pa.x));
            float2 ahi = __bfloat1622float2(*reinterpret_cast<__nv_bfloat162*>(&pa.y));
            float2 blo = __bfloat1622float2(*reinterpret_cast<__nv_bfloat162*>(&pbv.x));
            float2 bhi = __bfloat1622float2(*reinterpret_cast<__nv_bfloat162*>(&pbv.y));
            float4 v = make_float4(alo.x + blo.x, alo.y + blo.y, ahi.x + bhi.x, ahi.y + bhi.y);
            *(float4*)(xs + e * H + lane * 4) = v;
            if (lane < 4)
                *(float4*)(sea + e * 16 + lane * 4) = ((const float4*)(ea + (size_t)eg * 16))[lane];
        }
        __syncthreads();

        // ---- layer 1 (fp32): acc = b1 + xs + sea@W1c ; h1b = bf16(bn(relu(acc)))
        float acc[4][4];
        {
            float4 bbv = *(const float4*)(pb1 + c0);
#pragma unroll
            for (int jr = 0; jr < 4; jr++) {
                float4 xv = *(const float4*)(xs + (e0 + jr) * H + c0);
                acc[jr][0] = bbv.x + xv.x; acc[jr][1] = bbv.y + xv.y;
                acc[jr][2] = bbv.z + xv.z; acc[jr][3] = bbv.w + xv.w;
            }
        }
#pragma unroll
        for (int k = 0; k < 16; k += 4) {
            float4 s0 = *(const float4*)(sea + (e0 + 0) * 16 + k);
            float4 s1 = *(const float4*)(sea + (e0 + 1) * 16 + k);
            float4 s2 = *(const float4*)(sea + (e0 + 2) * 16 + k);
            float4 s3 = *(const float4*)(sea + (e0 + 3) * 16 + k);
#pragma unroll
            for (int kk = 0; kk < 4; kk++) {
                float4 wv = *(const float4*)(sW1c + (k + kk) * H + c0);
                float a0 = ((const float*)&s0)[kk];
                float a1 = ((const float*)&s1)[kk];
                float a2 = ((const float*)&s2)[kk];
                float a3 = ((const float*)&s3)[kk];
                acc[0][0] = fmaf(a0, wv.x, acc[0][0]); acc[0][1] = fmaf(a0, wv.y, acc[0][1]);
                acc[0][2] = fmaf(a0, wv.z, acc[0][2]); acc[0][3] = fmaf(a0, wv.w, acc[0][3]);
                acc[1][0] = fmaf(a1, wv.x, acc[1][0]); acc[1][1] = fmaf(a1, wv.y, acc[1][1]);
                acc[1][2] = fmaf(a1, wv.z, acc[1][2]); acc[1][3] = fmaf(a1, wv.w, acc[1][3]);
                acc[2][0] = fmaf(a2, wv.x, acc[2][0]); acc[2][1] = fmaf(a2, wv.y, acc[2][1]);
                acc[2][2] = fmaf(a2, wv.z, acc[2][2]); acc[2][3] = fmaf(a2, wv.w, acc[2][3]);
                acc[3][0] = fmaf(a3, wv.x, acc[3][0]); acc[3][1] = fmaf(a3, wv.y, acc[3][1]);
                acc[3][2] = fmaf(a3, wv.z, acc[3][2]); acc[3][3] = fmaf(a3, wv.w, acc[3][3]);
            }
        }
#pragma unroll
        for (int jr = 0; jr < 4; jr++) {
            float o[4];
#pragma unroll
            for (int jc = 0; jc < 4; jc++) {
                float z = fmaxf(acc[jr][jc], 0.0f);
                o[jc] = z * ps1[c0 + jc] + pt1[c0 + jc];
            }
            __nv_bfloat162 q0 = __floats2bfloat162_rn(o[0], o[1]);
            __nv_bfloat162 q1 = __floats2bfloat162_rn(o[2], o[3]);
            *(uint2*)(h1b + (e0 + jr) * 136 + c0) = make_uint2(*(unsigned*)&q0, *(unsigned*)&q1);
        }
        __syncthreads();

        // ---- layer 2 (bf16 mma): h2[32][64] = relu(h1 @ W2 + b2) ; h2 in xs stride 65
        float* h2 = xs;
        {
            float a2[2][4];
            int cA = nq2 * 16 + (lane & 3) * 2;
#pragma unroll
            for (int j = 0; j < 2; j++) {
                int c = cA + j * 8;
                a2[j][0] = pb2[c]; a2[j][1] = pb2[c + 1];
                a2[j][2] = pb2[c]; a2[j][3] = pb2[c + 1];
            }
            int ar2 = mt2 * 16 + (lane >> 2);
            int ac2 = (lane & 3) * 2;
#pragma unroll
            for (int ks = 0; ks < 8; ks++) {
                int kb = ks * 16;
                const __nv_bfloat16* abase = h1b + ar2 * 136 + kb + ac2;
                unsigned af[4];
                af[0] = *(const unsigned*)(abase);
                af[1] = *(const unsigned*)(abase + 8 * 136);
                af[2] = *(const unsigned*)(abase + 8);
                af[3] = *(const unsigned*)(abase + 8 * 136 + 8);
#pragma unroll
                for (int j = 0; j < 2; j++) {
                    int ncol = (nq2 * 2 + j) * 8 + (lane >> 2);
                    const __nv_bfloat16* bbase = sW2b + ncol * 136 + kb + ac2;
                    unsigned b0 = *(const unsigned*)(bbase);
                    unsigned b1 = *(const unsigned*)(bbase + 8);
                    mma16816(a2[j], af, b0, b1);
                }
            }
            __syncthreads();
            int r2 = mt2 * 16 + (lane >> 2);
#pragma unroll
            for (int j = 0; j < 2; j++) {
                int c = cA + j * 8;
                h2[r2 * 65 + c] = fmaxf(a2[j][0], 0.f);
                h2[r2 * 65 + c + 1] = fmaxf(a2[j][1], 0.f);
                h2[(r2 + 8) * 65 + c] = fmaxf(a2[j][2], 0.f);
                h2[(r2 + 8) * 65 + c + 1] = fmaxf(a2[j][3], 0.f);
            }
        }
        __syncthreads();

        // ---- layer 3 + sigmoid
#pragma unroll
        for (int e4 = 0; e4 < 4; e4++) {
            int e = w * 4 + e4;
            float part = h2[e * 65 + lane] * pW3[lane]
                       + h2[e * 65 + 32 + lane] * pW3[32 + lane];
#pragma unroll
            for (int off = 16; off; off >>= 1)
                part += __shfl_xor_sync(0xffffffffu, part, off);
            if (lane == 0)
                outp[base + e] = 1.0f / (1.0f + expf(-(part + pb3[0])));
        }
        __syncthreads();
    }
}

// ------------------------------- host ----------------------------------------
extern "C" void kernel_launch(void* const* d_in, const int* in_sizes, int n_in,
                              void* d_out, int out_size) {
    const float* x_user = (const float*)d_in[0];
    const float* x_recip = (const float*)d_in[1];
    const float* edge_attr = (const float*)d_in[2];
    const int* ei_ut = (const int*)d_in[3];
    const int* ei_ru = (const int*)d_in[4];
    const float* proj_uW = (const float*)d_in[5];
    const float* proj_ub = (const float*)d_in[6];
    const float* proj_rW = (const float*)d_in[7];
    const float* proj_rb = (const float*)d_in[8];
    const float* sage_Wl = (const float*)d_in[9];
    const float* sage_bl = (const float*)d_in[10];
    const float* sage_Wr = (const float*)d_in[11];
    const float* bn_g = (const float*)d_in[12];
    const float* bn_b = (const float*)d_in[13];
    const float* bn_m = (const float*)d_in[14];
    const float* bn_v = (const float*)d_in[15];
    const float* ep_W1 = (const float*)d_in[16];
    const float* ep_b1 = (const float*)d_in[17];
    const float* ep_bng = (const float*)d_in[18];
    const float* ep_bnb = (const float*)d_in[19];
    const float* ep_bnm = (const float*)d_in[20];
    const float* ep_bnv = (const float*)d_in[21];
    const float* ep_W2 = (const float*)d_in[22];
    const float* ep_b2 = (const float*)d_in[23];
    const float* ep_W3 = (const float*)d_in[24];
    const float* ep_b3 = (const float*)d_in[25];
    float* out = (float*)d_out;

    int Nu = in_sizes[0] / 32;
    int Nr = in_sizes[1] / 32;
    int E = in_sizes[3] / 2;

    const int* utSrc = ei_ut;
    const int* utDst = ei_ut + E;
    const int* ruSrc = ei_ru;
    const int* ruDst = ei_ru + E;

    float* hu; cudaGetSymbolAddress((void**)&hu, g_hu);
    float* hr; cudaGetSymbolAddress((void**)&hr, g_hr);
    float* aggR; cudaGetSymbolAddress((void**)&aggR, g_aggR);
    float* aggU; cudaGetSymbolAddress((void**)&aggU, g_aggU);
    float* cu; cudaGetSymbolAddress((void**)&cu, g_cu);
    float* cr; cudaGetSymbolAddress((void**)&cr, g_cr);
    __nv_bfloat16* Pub; cudaGetSymbolAddress((void**)&Pub, g_Pub);
    __nv_bfloat16* Prb; cudaGetSymbolAddress((void**)&Prb, g_Prb);

    const int SM1 = (128 * 264 * 2) * 2 + 256 * 4;                    // 136192
    const int SM2 = SM1 + 128 * 136 * 2;                              // 171008
    const int EP_SMEM = (2048 + 4096 + 512 + 384 + 64 + 64 + 4) * 4 + (64 * 136 + 32 * 136) * 2;
    cudaFuncSetAttribute(mma_pair_kernel<1>, cudaFuncAttributeMaxDynamicSharedMemorySize, SM1);
    cudaFuncSetAttribute(mma_pair_kernel<2>, cudaFuncAttributeMaxDynamicSharedMemorySize, SM2);
    cudaFuncSetAttribute(edgepred_kernel, cudaFuncAttributeMaxDynamicSharedMemorySize, EP_SMEM);

    const int T = 256;
    const int GRID_P = 148;
    int zn1 = Nr * 32, zn2 = Nu * 32, zn3 = Nr / 4, zn4 = Nu / 4;

    // 0: zero agg + counts
    zero_all_kernel<<<(zn1 + zn2 + zn3 + zn4 + T - 1) / T, T>>>(
        (float4*)aggR, zn1, (float4*)aggU, zn2, (float4*)cr, zn3, (float4*)cu, zn4);
    // 1: projections
    proj2_kernel<<<((Nu + Nr) * H + T - 1) / T, T>>>(x_user, proj_uW, proj_ub, hu, Nu,
                                                     x_recip, proj_rW, proj_rb, hr, Nr);
    // 2: scatter layer 0 (+ degree counting)
    scatter2_kernel<<<(2 * E * 8 + T - 1) / T, T>>>(hu, hr, utSrc, utDst, ruSrc, ruDst,
                                                    aggR, aggU, cr, cu, 1, E);

    GemmPair gp;
    gp.split = GRID_P / 2;
    gp.A[0] = aggR;  gp.A[1] = aggU;
    gp.cnt[0] = cr;  gp.cnt[1] = cu;
    gp.Bh[0] = hr;   gp.Bh[1] = hu;
    gp.M[0] = Nr;    gp.M[1] = Nu;

    // 3: layer-0 SAGE (zero agg rows for next layer)
    gp.zeroA = 1;
    gp.W1[0] = sage_Wl;                 gp.W1[1] = sage_Wl + (size_t)1 * H * H;
    gp.W2[0] = sage_Wr;                 gp.W2[1] = sage_Wr + (size_t)1 * H * H;
    gp.bias[0] = sage_bl;               gp.bias[1] = sage_bl + H;
    gp.bg[0] = bn_g + 1 * H;  gp.bg[1] = bn_g;
    gp.bb[0] = bn_b + 1 * H;  gp.bb[1] = bn_b;
    gp.bm[0] = bn_m + 1 * H;  gp.bm[1] = bn_m;
    gp.bv[0] = bn_v + 1 * H;  gp.bv[1] = bn_v;
    gp.Wep[0] = nullptr; gp.Wep[1] = nullptr;
    gp.Outb[0] = nullptr; gp.Outb[1] = nullptr;
    mma_pair_kernel<1><<<GRID_P, T, SM1>>>(gp);

    // 4: scatter layer 1 (agg zeroed by previous kernel)
    scatter2_kernel<<<(2 * E * 8 + T - 1) / T, T>>>(hu, hr, utSrc, utDst, ruSrc, ruDst,
                                                    aggR, aggU, cr, cu, 0, E);

    // 5: layer-1 SAGE with fused edge-predictor P computation
    gp.zeroA = 0;
    gp.W1[0] = sage_Wl + (size_t)2 * H * H;  gp.W1[1] = sage_Wl + (size_t)3 * H * H;
    gp.W2[0] = sage_Wr + (size_t)2 * H * H;  gp.W2[1] = sage_Wr + (size_t)3 * H * H;
    gp.bias[0] = sage_bl + 2 * H;            gp.bias[1] = sage_bl + 3 * H;
    gp.bg[0] = bn_g + 3 * H;  gp.bg[1] = bn_g + 2 * H;
    gp.bb[0] = bn_b + 3 * H;  gp.bb[1] = bn_b + 2 * H;
    gp.bm[0] = bn_m + 3 * H;  gp.bm[1] = bn_m + 2 * H;
    gp.bv[0] = bn_v + 3 * H;  gp.bv[1] = bn_v + 2 * H;
    gp.Wep[0] = ep_W1 + 128 * H;   // Pr = hr @ W1[128:256]
    gp.Wep[1] = ep_W1;             // Pu = hu @ W1[0:128]
    gp.Outb[0] = Prb;
    gp.Outb[1] = Pub;
    mma_pair_kernel<2><<<GRID_P, T, SM2>>>(gp);

    // 6: edge predictor
    edgepred_kernel<<<2 * GRID_P, T, EP_SMEM>>>(utSrc, utDst, edge_attr,
                                                Pub, Prb,
                                                ep_W1 + 256 * H, ep_b1,
                                                ep_bng, ep_bnb, ep_bnm, ep_bnv,
                                                ep_W2, ep_b2, ep_W3, ep_b3, out, E);
}

// round 14
// speedup vs baseline: 1.5219x; 1.5219x over previous
#include <cuda_runtime.h>
#include <cuda_bf16.h>
#include <math.h>

#define H 128
#define MAXN 100000
#define BN_EPS 1e-5f

// ---------------- scratch (device globals: no allocation allowed) -------------
__device__ __align__(16) float g_hu[(size_t)MAXN * H];
__device__ __align__(16) float g_hr[(size_t)MAXN * H];
__device__ __align__(16) float g_aggR[(size_t)MAXN * H];   // later reused as Pu (bf16 view)
__device__ __align__(16) float g_aggU[(size_t)MAXN * H];   // later reused as Pr (bf16 view)
__device__ __align__(16) float g_cu[MAXN];   // becomes 1/max(cnt,1)
__device__ __align__(16) float g_cr[MAXN];

// ---------------- small utility kernels --------------------------------------
__global__ void zero2_kernel(float4* __restrict__ p1, int n1, float4* __restrict__ p2, int n2) {
    int i = blockIdx.x * blockDim.x + threadIdx.x;
    float4 z = make_float4(0.f, 0.f, 0.f, 0.f);
    if (i < n1) p1[i] = z;
    else if (i < n1 + n2) p2[i - n1] = z;
}

__global__ void count2_kernel(const int* __restrict__ ruDst, const int* __restrict__ utDst,
                              int E, float* __restrict__ cu, float* __restrict__ cr) {
    int i = blockIdx.x * blockDim.x + threadIdx.x;
    if (i < E) atomicAdd(&cu[ruDst[i]], 1.0f);
    else if (i < 2 * E) atomicAdd(&cr[utDst[i - E]], 1.0f);
}

__global__ void inv2_kernel(float* __restrict__ c1, int n1, float* __restrict__ c2, int n2) {
    int i = blockIdx.x * blockDim.x + threadIdx.x;
    if (i < n1) c1[i] = 1.0f / fmaxf(c1[i], 1.0f);
    else if (i < n1 + n2) c2[i - n1] = 1.0f / fmaxf(c2[i - n1], 1.0f);
}

// y[n,H] = x[n,32] @ W[32,H] + b ; both node types in one launch
__global__ void proj2_kernel(const float* __restrict__ xu, const float* __restrict__ Wu,
                             const float* __restrict__ bu, float* __restrict__ yu, int nu,
                             const float* __restrict__ xr, const float* __restrict__ Wr,
                             const float* __restrict__ br, float* __restrict__ yr, int nr) {
    int i = blockIdx.x * blockDim.x + threadIdx.x;
    const float* x; const float* W; const float* b; float* y;
    if (i < nu * H) { x = xu; W = Wu; b = bu; y = yu; }
    else if (i < (nu + nr) * H) { i -= nu * H; x = xr; W = Wr; b = br; y = yr; }
    else return;
    int row = i >> 7;
    int c = i & (H - 1);
    const float* xr_ = x + (size_t)row * 32;
    float acc = b[c];
#pragma unroll
    for (int k = 0; k < 32; k++) acc = fmaf(xr_[k], W[k * H + c], acc);
    y[i] = acc;
}

// Both scatters in one launch; fp32 v4 reductions; 4 edges/warp (MLP=4).
__global__ void scatter2_kernel(const float* __restrict__ hu, const float* __restrict__ hr,
                                const int* __restrict__ utSrc, const int* __restrict__ utDst,
                                const int* __restrict__ ruSrc, const int* __restrict__ ruDst,
                                float* __restrict__ aggR, float* __restrict__ aggU, int E) {
    int t = blockIdx.x * blockDim.x + threadIdx.x;
    int warp = t >> 5;
    int j = t & 31;
    int e0 = warp * 4;
    if (e0 >= 2 * E) return;

    const float* hp[4];
    float* ap[4];
    bool ok[4];
#pragma unroll
    for (int k = 0; k < 4; k++) {
        int e = e0 + k;
        ok[k] = e < 2 * E;
        if (ok[k]) {
            int s, d;
            if (e < E) {
                s = utSrc[e]; d = utDst[e];
                hp[k] = hu + (size_t)s * H;
                ap[k] = aggR + (size_t)d * H;
            } else {
                s = ruSrc[e - E]; d = ruDst[e - E];
                hp[k] = hr + (size_t)s * H;
                ap[k] = aggU + (size_t)d * H;
            }
        }
    }
    float4 v[4];
#pragma unroll
    for (int k = 0; k < 4; k++)
        if (ok[k]) v[k] = ((const float4*)hp[k])[j];
#pragma unroll
    for (int k = 0; k < 4; k++)
        if (ok[k]) {
            float* p = ap[k] + j * 4;
            asm volatile("red.global.add.v4.f32 [%0], {%1, %2, %3, %4};"
                         :: "l"(p), "f"(v[k].x), "f"(v[k].y), "f"(v[k].z), "f"(v[k].w) : "memory");
        }
}

// ------------------------ bf16 tensor-core GEMM -------------------------------
__device__ __forceinline__ void mma16816(float* d, const unsigned* a, unsigned b0, unsigned b1) {
    asm volatile("mma.sync.aligned.m16n8k16.row.col.f32.bf16.bf16.f32 "
                 "{%0,%1,%2,%3}, {%4,%5,%6,%7}, {%8,%9}, {%0,%1,%2,%3};"
                 : "+f"(d[0]), "+f"(d[1]), "+f"(d[2]), "+f"(d[3])
                 : "r"(a[0]), "r"(a[1]), "r"(a[2]), "r"(a[3]), "r"(b0), "r"(b1));
}

// Two independent GEMM problems fused in one launch, split by block range.
struct GemmPair {
    const float* A[2];
    const float* invc[2];
    float* Bh[2];
    __nv_bfloat16* Outb[2];           // MODE0: bf16 output
    const float* W1[2];
    const float* W2[2];
    const float* bias[2];
    const float* bg[2];
    const float* bb[2];
    const float* bm[2];
    const float* bv[2];
    int M[2];
    int split;   // blocks [0,split) -> problem 0, [split, grid) -> problem 1
};

// 512 threads = 16 warps; warp_m = wid>>1 (16 rows each), warp_n = wid&1 (64 cols).
// MODE 0: Outb = bf16( A @ W1 )     (K = 128)
// MODE 1: Bh  = relu(bn( [A*invc | Bh] @ [W1;W2] + bias )) + Bh   (K = 256)
template <int KT, int MODE>
__global__ void __launch_bounds__(512)
mma_pair_kernel(GemmPair p) {
    constexpr int K = KT * 16;
    constexpr int KPAD = K + 8;
    extern __shared__ __align__(16) unsigned char smraw[];
    __nv_bfloat16* sWt = (__nv_bfloat16*)smraw;                 // [128][KPAD]  (n-major)
    __nv_bfloat16* sA = sWt + 128 * KPAD;                       // [128][KPAD]  (row-major)
    float* sS = (float*)(sA + 128 * KPAD);                      // 128
    float* sT = sS + 128;                                       // 128

    int hsel = blockIdx.x >= p.split ? 1 : 0;
    int b0 = hsel ? blockIdx.x - p.split : blockIdx.x;
    int nb = hsel ? gridDim.x - p.split : p.split;
    const float* A = p.A[hsel];
    const float* invc = p.invc[hsel];
    float* Bh = p.Bh[hsel];
    __nv_bfloat16* Outb = p.Outb[hsel];
    const float* W1 = p.W1[hsel];
    const float* W2 = p.W2[hsel];
    int M = p.M[hsel];

    int tid = threadIdx.x;
    int lane = tid & 31;
    int wid = tid >> 5;
    int warp_m = wid >> 1;      // 0..7  -> 16 rows each
    int warp_n = wid & 1;       // 0..1  -> 64 cols each

    for (int i = tid; i < K * 128; i += 512) {
        int k = i >> 7;
        int n = i & 127;
        float w = (MODE == 1 && k >= 128) ? W2[(k - 128) * 128 + n] : W1[k * 128 + n];
        sWt[n * KPAD + k] = __float2bfloat16(w);
    }
    if (MODE == 1 && tid < 128) {
        float s = p.bg[hsel][tid] * rsqrtf(p.bv[hsel][tid] + BN_EPS);
        sS[tid] = s;
        sT[tid] = (p.bias[hsel][tid] - p.bm[hsel][tid]) * s + p.bb[hsel][tid];
    }
    __syncthreads();

    int numTiles = (M + 127) >> 7;
    for (int tile = b0; tile < numTiles; tile += nb) {
        int row0 = tile * 128;
        for (int i = tid; i < 128 * 32; i += 512) {
            int r = i >> 5;
            int q = i & 31;
            int row = row0 + r;
            float4 a = make_float4(0.f, 0.f, 0.f, 0.f);
            if (row < M) {
                a = ((const float4*)(A + (size_t)row * H))[q];
                if (MODE == 1) {
                    float sc = invc[row];
                    a.x *= sc; a.y *= sc; a.z *= sc; a.w *= sc;
                }
            }
            __nv_bfloat162 p0 = __floats2bfloat162_rn(a.x, a.y);
            __nv_bfloat162 p1 = __floats2bfloat162_rn(a.z, a.w);
            *(uint2*)(sA + r * KPAD + q * 4) = make_uint2(*(unsigned*)&p0, *(unsigned*)&p1);
            if (MODE == 1) {
                float4 hv = make_float4(0.f, 0.f, 0.f, 0.f);
                if (row < M) hv = ((const float4*)(Bh + (size_t)row * H))[q];
                __nv_bfloat162 q0 = __floats2bfloat162_rn(hv.x, hv.y);
                __nv_bfloat162 q1 = __floats2bfloat162_rn(hv.z, hv.w);
                *(uint2*)(sA + r * KPAD + 128 + q * 4) = make_uint2(*(unsigned*)&q0, *(unsigned*)&q1);
            }
        }
        __syncthreads();

        float acc[8][4];
#pragma unroll
        for (int nt = 0; nt < 8; nt++)
#pragma unroll
            for (int j = 0; j < 4; j++) acc[nt][j] = 0.f;

        int ar = warp_m * 16 + (lane >> 2);
        int ac = (lane & 3) * 2;
#pragma unroll
        for (int ks = 0; ks < KT; ks++) {
            int kb = ks * 16;
            unsigned a[4];
            {
                const __nv_bfloat16* base = sA + ar * KPAD + kb + ac;
                a[0] = *(const unsigned*)(base);
                a[1] = *(const unsigned*)(base + 8 * KPAD);
                a[2] = *(const unsigned*)(base + 8);
                a[3] = *(const unsigned*)(base + 8 * KPAD + 8);
            }
#pragma unroll
            for (int nt = 0; nt < 8; nt++) {
                const __nv_bfloat16* bbase = sWt + (warp_n * 64 + nt * 8 + (lane >> 2)) * KPAD + kb + ac;
                unsigned b0 = *(const unsigned*)(bbase);
                unsigned b1 = *(const unsigned*)(bbase + 8);
                mma16816(acc[nt], a, b0, b1);
            }
        }

        int rbase = row0 + warp_m * 16 + (lane >> 2);
        int cbase = warp_n * 64 + (lane & 3) * 2;
#pragma unroll
        for (int half = 0; half < 2; half++) {
            int row = rbase + half * 8;
            if (row < M) {
#pragma unroll
                for (int nt = 0; nt < 8; nt++) {
                    int c = cbase + nt * 8;
                    float v0 = acc[nt][half * 2 + 0];
                    float v1 = acc[nt][half * 2 + 1];
                    if (MODE == 1) {
                        v0 = v0 * sS[c] + sT[c];
                        v1 = v1 * sS[c + 1] + sT[c + 1];
                        float2 hres = *(const float2*)(Bh + (size_t)row * H + c);
                        float2 o = make_float2(fmaxf(v0, 0.f) + hres.x, fmaxf(v1, 0.f) + hres.y);
                        *(float2*)(Bh + (size_t)row * H + c) = o;
                    } else {
                        __nv_bfloat162 ob = __floats2bfloat162_rn(v0, v1);
                        *(unsigned*)(Outb + (size_t)row * H + c) = *(unsigned*)&ob;
                    }
                }
            }
        }
        __syncthreads();
    }
}

// Fused edge predictor; Pu/Pr gathered as bf16; layer 2 on bf16 mma; layer 3 warp-parallel.
__global__ void __launch_bounds__(256, 2)
edgepred_kernel(const int* __restrict__ utSrc, const int* __restrict__ utDst,
                const float* __restrict__ ea,
                const __nv_bfloat16* __restrict__ Pub, const __nv_bfloat16* __restrict__ Prb,
                const float* __restrict__ W1c, const float* __restrict__ b1,
                const float* __restrict__ bng, const float* __restrict__ bnb,
                const float* __restrict__ bnm, const float* __restrict__ bnv,
                const float* __restrict__ W2, const float* __restrict__ b2,
                const float* __restrict__ W3, const float* __restrict__ b3,
                float* __restrict__ outp, int E) {
    extern __shared__ __align__(16) unsigned char smroot[];
    float* sW1c = (float*)smroot;                 // 2048 f32
    float* xs = sW1c + 2048;                      // 32*128 f32 (reused as h2 [32][65])
    float* sea = xs + 4096;                       // 32*16 f32
    float* pb1 = sea + 512;                       // 128
    float* ps1 = pb1 + 128;                       // 128
    float* pt1 = ps1 + 128;                       // 128
    float* pb2 = pt1 + 128;                       // 64
    float* pW3 = pb2 + 64;                        // 64
    float* pb3 = pW3 + 64;                        // 4 (padded)
    __nv_bfloat16* sW2b = (__nv_bfloat16*)(pb3 + 4);   // [64][136] bf16, n-major
    __nv_bfloat16* h1b = sW2b + 64 * 136;              // [32][136] bf16

    int tid = threadIdx.x;
    int lane = tid & 31;
    int w = tid >> 5;

    for (int i = tid; i < 2048 / 4; i += 256)
        ((float4*)sW1c)[i] = ((const float4*)W1c)[i];
    for (int i = tid; i < 128 * 64; i += 256) {
        int k = i >> 6;
        int n = i & 63;
        sW2b[n * 136 + k] = __float2bfloat16(W2[k * 64 + n]);
    }
    if (tid < 128) {
        pb1[tid] = b1[tid];
        float s = bng[tid] * rsqrtf(bnv[tid] + BN_EPS);
        ps1[tid] = s;
        pt1[tid] = bnb[tid] - bnm[tid] * s;
    } else if (tid < 192) {
        pb2[tid - 128] = b2[tid - 128];
    } else {
        pW3[tid - 192] = W3[tid - 192];
    }
    if (tid == 0) pb3[0] = b3[0];
    __syncthreads();

    int tc = tid & 31;
    int te = tid >> 5;
    int c0 = tc * 4;
    int e0 = te * 4;
    int mt2 = w >> 2;
    int nq2 = w & 3;

    int numTiles = E / 32;
    for (int tile = blockIdx.x; tile < numTiles; tile += gridDim.x) {
        int base = tile * 32;
#pragma unroll
        for (int i = 0; i < 4; i++) {
            int e = w * 4 + i;
            int eg = base + e;
            int s = utSrc[eg];
            int d = utDst[eg];
            uint2 pa = ((const uint2*)(Pub + (size_t)s * H))[lane];
            uint2 pbv = ((const uint2*)(Prb + (size_t)d * H))[lane];
            float2 alo = __bfloat1622float2(*reinterpret_cast<__nv_bfloat162*>(&pa.x));
            float2 ahi = __bfloat1622float2(*reinterpret_cast<__nv_bfloat162*>(&pa.y));
            float2 blo = __bfloat1622float2(*reinterpret_cast<__nv_bfloat162*>(&pbv.x));
            float2 bhi = __bfloat1622float2(*reinterpret_cast<__nv_bfloat162*>(&pbv.y));
            float4 v = make_float4(alo.x + blo.x, alo.y + blo.y, ahi.x + bhi.x, ahi.y + bhi.y);
            *(float4*)(xs + e * H + lane * 4) = v;
            if (lane < 4)
                *(float4*)(sea + e * 16 + lane * 4) = ((const float4*)(ea + (size_t)eg * 16))[lane];
        }
        __syncthreads();

        // ---- layer 1 (fp32): acc = b1 + xs + sea@W1c ; h1b = bf16(bn(relu(acc)))
        float acc[4][4];
        {
            float4 bbv = *(const float4*)(pb1 + c0);
#pragma unroll
            for (int jr = 0; jr < 4; jr++) {
                float4 xv = *(const float4*)(xs + (e0 + jr) * H + c0);
                acc[jr][0] = bbv.x + xv.x; acc[jr][1] = bbv.y + xv.y;
                acc[jr][2] = bbv.z + xv.z; acc[jr][3] = bbv.w + xv.w;
            }
        }
#pragma unroll
        for (int k = 0; k < 16; k += 4) {
            float4 s0 = *(const float4*)(sea + (e0 + 0) * 16 + k);
            float4 s1 = *(const float4*)(sea + (e0 + 1) * 16 + k);
            float4 s2 = *(const float4*)(sea + (e0 + 2) * 16 + k);
            float4 s3 = *(const float4*)(sea + (e0 + 3) * 16 + k);
#pragma unroll
            for (int kk = 0; kk < 4; kk++) {
                float4 wv = *(const float4*)(sW1c + (k + kk) * H + c0);
                float a0 = ((const float*)&s0)[kk];
                float a1 = ((const float*)&s1)[kk];
                float a2 = ((const float*)&s2)[kk];
                float a3 = ((const float*)&s3)[kk];
                acc[0][0] = fmaf(a0, wv.x, acc[0][0]); acc[0][1] = fmaf(a0, wv.y, acc[0][1]);
                acc[0][2] = fmaf(a0, wv.z, acc[0][2]); acc[0][3] = fmaf(a0, wv.w, acc[0][3]);
                acc[1][0] = fmaf(a1, wv.x, acc[1][0]); acc[1][1] = fmaf(a1, wv.y, acc[1][1]);
                acc[1][2] = fmaf(a1, wv.z, acc[1][2]); acc[1][3] = fmaf(a1, wv.w, acc[1][3]);
                acc[2][0] = fmaf(a2, wv.x, acc[2][0]); acc[2][1] = fmaf(a2, wv.y, acc[2][1]);
                acc[2][2] = fmaf(a2, wv.z, acc[2][2]); acc[2][3] = fmaf(a2, wv.w, acc[2][3]);
                acc[3][0] = fmaf(a3, wv.x, acc[3][0]); acc[3][1] = fmaf(a3, wv.y, acc[3][1]);
                acc[3][2] = fmaf(a3, wv.z, acc[3][2]); acc[3][3] = fmaf(a3, wv.w, acc[3][3]);
            }
        }
#pragma unroll
        for (int jr = 0; jr < 4; jr++) {
            float o[4];
#pragma unroll
            for (int jc = 0; jc < 4; jc++) {
                float z = fmaxf(acc[jr][jc], 0.0f);
                o[jc] = z * ps1[c0 + jc] + pt1[c0 + jc];
            }
            __nv_bfloat162 q0 = __floats2bfloat162_rn(o[0], o[1]);
            __nv_bfloat162 q1 = __floats2bfloat162_rn(o[2], o[3]);
            *(uint2*)(h1b + (e0 + jr) * 136 + c0) = make_uint2(*(unsigned*)&q0, *(unsigned*)&q1);
        }
        __syncthreads();

        // ---- layer 2 (bf16 mma): h2[32][64] = relu(h1 @ W2 + b2) ; h2 in xs stride 65
        float* h2 = xs;
        {
            float a2[2][4];
            int cA = nq2 * 16 + (lane & 3) * 2;
#pragma unroll
            for (int j = 0; j < 2; j++) {
                int c = cA + j * 8;
                a2[j][0] = pb2[c]; a2[j][1] = pb2[c + 1];
                a2[j][2] = pb2[c]; a2[j][3] = pb2[c + 1];
            }
            int ar2 = mt2 * 16 + (lane >> 2);
            int ac2 = (lane & 3) * 2;
#pragma unroll
            for (int ks = 0; ks < 8; ks++) {
                int kb = ks * 16;
                const __nv_bfloat16* abase = h1b + ar2 * 136 + kb + ac2;
                unsigned af[4];
                af[0] = *(const unsigned*)(abase);
                af[1] = *(const unsigned*)(abase + 8 * 136);
                af[2] = *(const unsigned*)(abase + 8);
                af[3] = *(const unsigned*)(abase + 8 * 136 + 8);
#pragma unroll
                for (int j = 0; j < 2; j++) {
                    int ncol = (nq2 * 2 + j) * 8 + (lane >> 2);
                    const __nv_bfloat16* bbase = sW2b + ncol * 136 + kb + ac2;
                    unsigned b0 = *(const unsigned*)(bbase);
                    unsigned b1 = *(const unsigned*)(bbase + 8);
                    mma16816(a2[j], af, b0, b1);
                }
            }
            __syncthreads();
            int r2 = mt2 * 16 + (lane >> 2);
#pragma unroll
            for (int j = 0; j < 2; j++) {
                int c = cA + j * 8;
                h2[r2 * 65 + c] = fmaxf(a2[j][0], 0.f);
                h2[r2 * 65 + c + 1] = fmaxf(a2[j][1], 0.f);
                h2[(r2 + 8) * 65 + c] = fmaxf(a2[j][2], 0.f);
                h2[(r2 + 8) * 65 + c + 1] = fmaxf(a2[j][3], 0.f);
            }
        }
        __syncthreads();

        // ---- layer 3 + sigmoid
#pragma unroll
        for (int e4 = 0; e4 < 4; e4++) {
            int e = w * 4 + e4;
            float part = h2[e * 65 + lane] * pW3[lane]
                       + h2[e * 65 + 32 + lane] * pW3[32 + lane];
#pragma unroll
            for (int off = 16; off; off >>= 1)
                part += __shfl_xor_sync(0xffffffffu, part, off);
            if (lane == 0)
                outp[base + e] = 1.0f / (1.0f + expf(-(part + pb3[0])));
        }
        __syncthreads();
    }
}

// ------------------------------- host ----------------------------------------
extern "C" void kernel_launch(void* const* d_in, const int* in_sizes, int n_in,
                              void* d_out, int out_size) {
    const float* x_user = (const float*)d_in[0];
    const float* x_recip = (const float*)d_in[1];
    const float* edge_attr = (const float*)d_in[2];
    const int* ei_ut = (const int*)d_in[3];
    const int* ei_ru = (const int*)d_in[4];
    const float* proj_uW = (const float*)d_in[5];
    const float* proj_ub = (const float*)d_in[6];
    const float* proj_rW = (const float*)d_in[7];
    const float* proj_rb = (const float*)d_in[8];
    const float* sage_Wl = (const float*)d_in[9];
    const float* sage_bl = (const float*)d_in[10];
    const float* sage_Wr = (const float*)d_in[11];
    const float* bn_g = (const float*)d_in[12];
    const float* bn_b = (const float*)d_in[13];
    const float* bn_m = (const float*)d_in[14];
    const float* bn_v = (const float*)d_in[15];
    const float* ep_W1 = (const float*)d_in[16];
    const float* ep_b1 = (const float*)d_in[17];
    const float* ep_bng = (const float*)d_in[18];
    const float* ep_bnb = (const float*)d_in[19];
    const float* ep_bnm = (const float*)d_in[20];
    const float* ep_bnv = (const float*)d_in[21];
    const float* ep_W2 = (const float*)d_in[22];
    const float* ep_b2 = (const float*)d_in[23];
    const float* ep_W3 = (const float*)d_in[24];
    const float* ep_b3 = (const float*)d_in[25];
    float* out = (float*)d_out;

    int Nu = in_sizes[0] / 32;
    int Nr = in_sizes[1] / 32;
    int E = in_sizes[3] / 2;

    const int* utSrc = ei_ut;
    const int* utDst = ei_ut + E;
    const int* ruSrc = ei_ru;
    const int* ruDst = ei_ru + E;

    float* hu; cudaGetSymbolAddress((void**)&hu, g_hu);
    float* hr; cudaGetSymbolAddress((void**)&hr, g_hr);
    float* aggR; cudaGetSymbolAddress((void**)&aggR, g_aggR);
    float* aggU; cudaGetSymbolAddress((void**)&aggU, g_aggU);
    float* cu; cudaGetSymbolAddress((void**)&cu, g_cu);
    float* cr; cudaGetSymbolAddress((void**)&cr, g_cr);
    __nv_bfloat16* Pub = (__nv_bfloat16*)aggR;   // bf16 views for edge-pred precompute
    __nv_bfloat16* Prb = (__nv_bfloat16*)aggU;

    const int SM1 = (128 * 264 * 2) * 2 + 256 * 4;
    const int SM0 = (128 * 136 * 2) * 2;
    const int EP_SMEM = (2048 + 4096 + 512 + 384 + 64 + 64 + 4) * 4 + (64 * 136 + 32 * 136) * 2;
    cudaFuncSetAttribute(mma_pair_kernel<16, 1>, cudaFuncAttributeMaxDynamicSharedMemorySize, SM1);
    cudaFuncSetAttribute(mma_pair_kernel<8, 0>, cudaFuncAttributeMaxDynamicSharedMemorySize, SM0);
    cudaFuncSetAttribute(edgepred_kernel, cudaFuncAttributeMaxDynamicSharedMemorySize, EP_SMEM);

    const int T = 256;
    const int TG = 512;
    const int GRID_P = 148;
    int zn1 = Nr * 32, zn2 = Nu * 32;

    // 0: zero agg (layer 0)
    zero2_kernel<<<(zn1 + zn2 + T - 1) / T, T>>>((float4*)aggR, zn1, (float4*)aggU, zn2);
    // 1: zero counts
    zero2_kernel<<<((Nu + Nr) / 4 + T - 1) / T, T>>>((float4*)cu, Nu / 4, (float4*)cr, Nr / 4);
    // 2: projections
    proj2_kernel<<<((Nu + Nr) * H + T - 1) / T, T>>>(x_user, proj_uW, proj_ub, hu, Nu,
                                                     x_recip, proj_rW, proj_rb, hr, Nr);
    // 3: scatter layer 0  <-- profile target (4 edges per warp, MLP=4)
    scatter2_kernel<<<(2 * E * 8 + T - 1) / T, T>>>(hu, hr, utSrc, utDst, ruSrc, ruDst,
                                                    aggR, aggU, E);
    // 4-5: degree counts + inverse
    count2_kernel<<<(2 * E + T - 1) / T, T>>>(ruDst, utDst, E, cu, cr);
    inv2_kernel<<<(Nu + Nr + T - 1) / T, T>>>(cu, Nu, cr, Nr);

    GemmPair gp;
    gp.split = GRID_P / 2;
    for (int i = 0; i < 2; i++) {
        gp.A[0] = aggR;  gp.A[1] = aggU;
        gp.invc[0] = cr; gp.invc[1] = cu;
        gp.Bh[0] = hr;   gp.Bh[1] = hu;
        gp.Outb[0] = nullptr; gp.Outb[1] = nullptr;
        gp.W1[0] = sage_Wl + (size_t)(i * 2 + 0) * H * H;
        gp.W1[1] = sage_Wl + (size_t)(i * 2 + 1) * H * H;
        gp.W2[0] = sage_Wr + (size_t)(i * 2 + 0) * H * H;
        gp.W2[1] = sage_Wr + (size_t)(i * 2 + 1) * H * H;
        gp.bias[0] = sage_bl + (size_t)(i * 2 + 0) * H;
        gp.bias[1] = sage_bl + (size_t)(i * 2 + 1) * H;
        gp.bg[0] = bn_g + (i * 2 + 1) * H; gp.bg[1] = bn_g + (i * 2 + 0) * H;
        gp.bb[0] = bn_b + (i * 2 + 1) * H; gp.bb[1] = bn_b + (i * 2 + 0) * H;
        gp.bm[0] = bn_m + (i * 2 + 1) * H; gp.bm[1] = bn_m + (i * 2 + 0) * H;
        gp.bv[0] = bn_v + (i * 2 + 1) * H; gp.bv[1] = bn_v + (i * 2 + 0) * H;
        gp.M[0] = Nr; gp.M[1] = Nu;
        mma_pair_kernel<16, 1><<<GRID_P, TG, SM1>>>(gp);

        if (i == 0) {
            zero2_kernel<<<(zn1 + zn2 + T - 1) / T, T>>>((float4*)aggR, zn1, (float4*)aggU, zn2);
            scatter2_kernel<<<(2 * E * 8 + T - 1) / T, T>>>(hu, hr, utSrc, utDst, ruSrc, ruDst,
                                                            aggR, aggU, E);
        }
    }

    // fused edge-predictor precompute (bf16 out): Pub = hu@W1[0:128], Prb = hr@W1[128:256]
    GemmPair g0;
    g0.split = GRID_P;
    g0.A[0] = hu;  g0.A[1] = hr;
    g0.invc[0] = nullptr; g0.invc[1] = nullptr;
    g0.Bh[0] = nullptr;   g0.Bh[1] = nullptr;
    g0.Outb[0] = Pub;     g0.Outb[1] = Prb;
    g0.W1[0] = ep_W1;     g0.W1[1] = ep_W1 + 128 * H;
    g0.W2[0] = nullptr;   g0.W2[1] = nullptr;
    g0.bias[0] = nullptr; g0.bias[1] = nullptr;
    g0.bg[0] = nullptr; g0.bg[1] = nullptr;
    g0.bb[0] = nullptr; g0.bb[1] = nullptr;
    g0.bm[0] = nullptr; g0.bm[1] = nullptr;
    g0.bv[0] = nullptr; g0.bv[1] = nullptr;
    g0.M[0] = Nu; g0.M[1] = Nr;
    mma_pair_kernel<8, 0><<<2 * GRID_P, TG, SM0>>>(g0);

    edgepred_kernel<<<2 * GRID_P, T, EP_SMEM>>>(utSrc, utDst, edge_attr,
                                                Pub, Prb,
                                                ep_W1 + 256 * H, ep_b1,
                                                ep_bng, ep_bnb, ep_bnm, ep_bnv,
                                                ep_W2, ep_b2, ep_W3, ep_b3, out, E);
}